// round 7
// baseline (speedup 1.0000x reference)
#include <cuda_runtime.h>
#include <cuda_fp16.h>
#include <math.h>

#define NA   65536
#define MM   12
#define ORIG 92
#define NBR  41
#define AF   64
#define G2   128      // 2*AF
#define KTOT 169
#define NCONV 3
#define HF   128
#define NC0  1024     // crystals
#define APC  64       // atoms per crystal
#define EPSB 1e-5f

// ---------------- scratch (device globals) ----------------
__device__ float  g_afea[(size_t)NA * AF];
__device__ float  g_sp[(size_t)NA * G2];
__device__ float  g_np[(size_t)NA * G2];
__device__ __half g_gatedh[(size_t)NA * MM * G2];    // 201 MB
__device__ float  g_nbrsum[(size_t)NA * AF];
__device__ float  g_stats1[2 * G2];
__device__ float  g_stats2[2 * AF];
__device__ float  g_pool[NC0 * AF];

__device__ __forceinline__ float splus(float x) {
    return fmaxf(x, 0.f) + __logf(1.f + __expf(-fabsf(x)));
}
__device__ __forceinline__ float sigm(float x) {
    return __fdividef(1.f, 1.f + __expf(-x));
}

// ---------------- embedding: (NA x 92) @ (92 x 64) + b ----------------
__global__ void k_embed(const float* __restrict__ A, const float* __restrict__ W,
                        const float* __restrict__ bias) {
    __shared__ float Wsm[ORIG * AF];
    __shared__ float Asm[64 * ORIG];
    int t = threadIdx.x;
    int n0 = blockIdx.x * 64;
    for (int idx = t; idx < ORIG * AF; idx += 256) Wsm[idx] = W[idx];
    for (int idx = t; idx < 64 * ORIG; idx += 256) Asm[idx] = A[(size_t)n0 * ORIG + idx];
    __syncthreads();
    int c0 = (t & 15) * 4;
    int r0 = (t >> 4) * 4;
    float acc[4][4];
#pragma unroll
    for (int i = 0; i < 4; i++)
#pragma unroll
        for (int j = 0; j < 4; j++) acc[i][j] = 0.f;
    for (int f = 0; f < ORIG; f++) {
        float4 w = *(const float4*)&Wsm[f * AF + c0];
#pragma unroll
        for (int i = 0; i < 4; i++) {
            float a = Asm[(r0 + i) * ORIG + f];
            acc[i][0] += a * w.x; acc[i][1] += a * w.y;
            acc[i][2] += a * w.z; acc[i][3] += a * w.w;
        }
    }
    float4 bv = *(const float4*)&bias[c0];
#pragma unroll
    for (int i = 0; i < 4; i++) {
        float4 o;
        o.x = acc[i][0] + bv.x; o.y = acc[i][1] + bv.y;
        o.z = acc[i][2] + bv.z; o.w = acc[i][3] + bv.w;
        *(float4*)&g_afea[(size_t)(n0 + r0 + i) * AF + c0] = o;
    }
}

// ---------------- self + neighbor parts (also zeroes BN stats) ----------------
__global__ void k_selfnbr(const float* __restrict__ W) {
    extern __shared__ float sm[];
    float* Wsm = sm;               // [64][256]
    float* Asm = sm + 64 * 256;    // [64][64]
    int t = threadIdx.x;
    int n0 = blockIdx.x * 64;
    if (blockIdx.x == 0) {
        if (t < 2 * G2) g_stats1[t] = 0.f;
        if (t < 2 * AF) g_stats2[t] = 0.f;
    }
    for (int idx = t; idx < 64 * 256; idx += 256) {
        int f = idx >> 8, c = idx & 255;
        Wsm[idx] = (c < G2) ? W[f * G2 + c] : W[(AF + f) * G2 + (c - G2)];
    }
    {
        const float4* src = (const float4*)(g_afea + (size_t)n0 * AF);
        float4* dst = (float4*)Asm;
        for (int idx = t; idx < 64 * AF / 4; idx += 256) dst[idx] = src[idx];
    }
    __syncthreads();
    int c0 = (t & 31) * 4;
    int r0 = (t >> 5) * 8;
    float accS[8][4], accN[8][4];
#pragma unroll
    for (int i = 0; i < 8; i++)
#pragma unroll
        for (int j = 0; j < 4; j++) { accS[i][j] = 0.f; accN[i][j] = 0.f; }
    for (int f = 0; f < AF; f++) {
        float4 ws = *(const float4*)&Wsm[f * 256 + c0];
        float4 wn = *(const float4*)&Wsm[f * 256 + G2 + c0];
#pragma unroll
        for (int i = 0; i < 8; i++) {
            float a = Asm[(r0 + i) * AF + f];
            accS[i][0] += a * ws.x; accS[i][1] += a * ws.y;
            accS[i][2] += a * ws.z; accS[i][3] += a * ws.w;
            accN[i][0] += a * wn.x; accN[i][1] += a * wn.y;
            accN[i][2] += a * wn.z; accN[i][3] += a * wn.w;
        }
    }
#pragma unroll
    for (int i = 0; i < 8; i++) {
        size_t n = (size_t)(n0 + r0 + i);
        float4 os; os.x = accS[i][0]; os.y = accS[i][1]; os.z = accS[i][2]; os.w = accS[i][3];
        float4 on; on.x = accN[i][0]; on.y = accN[i][1]; on.z = accN[i][2]; on.w = accN[i][3];
        *(float4*)&g_sp[n * G2 + c0] = os;
        *(float4*)&g_np[n * G2 + c0] = on;
    }
}

// ---------------- edge GEMM + assemble gated (fp16) + BN1 stats ----------------
// 128 edges/block; per thread 8 rows x 8 cols: 64 FMA per 10 LDS.
__global__ void __launch_bounds__(256) k_edgegated(
        const float* __restrict__ W, const float* __restrict__ bias,
        const float* __restrict__ nbr_fea, const int* __restrict__ nbr_idx) {
    extern __shared__ float sm[];
    float* Wesm = sm;                        // [41][128]
    float* Esm  = sm + NBR * G2;             // [128][41]
    float* red  = sm + NBR * G2 + 128 * NBR; // [8][256]
    int t = threadIdx.x;
    int q0 = blockIdx.x * 128;
    for (int idx = t; idx < NBR * G2; idx += 256) Wesm[idx] = W[G2 * G2 + idx];
    for (int idx = t; idx < 128 * NBR; idx += 256) Esm[idx] = nbr_fea[(size_t)q0 * NBR + idx];
    __syncthreads();
    int c0 = (t & 15) * 8;     // 16 col groups * 8 = 128 cols
    int r0 = (t >> 4) * 8;     // 16 row groups * 8 = 128 rows
    float acc[8][8];
#pragma unroll
    for (int i = 0; i < 8; i++)
#pragma unroll
        for (int j = 0; j < 8; j++) acc[i][j] = 0.f;
    for (int f = 0; f < NBR; f++) {
        float4 wa = *(const float4*)&Wesm[f * G2 + c0];
        float4 wb = *(const float4*)&Wesm[f * G2 + c0 + 4];
#pragma unroll
        for (int i = 0; i < 8; i++) {
            float e = Esm[(r0 + i) * NBR + f];
            acc[i][0] += e * wa.x; acc[i][1] += e * wa.y;
            acc[i][2] += e * wa.z; acc[i][3] += e * wa.w;
            acc[i][4] += e * wb.x; acc[i][5] += e * wb.y;
            acc[i][6] += e * wb.z; acc[i][7] += e * wb.w;
        }
    }
    float4 bva = *(const float4*)&bias[c0];
    float4 bvb = *(const float4*)&bias[c0 + 4];
    float cs[8], cq[8];
#pragma unroll
    for (int k = 0; k < 8; k++) { cs[k] = 0.f; cq[k] = 0.f; }
#pragma unroll
    for (int i = 0; i < 8; i++) {
        int q = q0 + r0 + i;
        int n = q / MM;
        int j = __ldg(&nbr_idx[q]);
        float4 sa = *(const float4*)&g_sp[(size_t)n * G2 + c0];
        float4 sb = *(const float4*)&g_sp[(size_t)n * G2 + c0 + 4];
        float4 na = *(const float4*)&g_np[(size_t)j * G2 + c0];
        float4 nb = *(const float4*)&g_np[(size_t)j * G2 + c0 + 4];
        float o[8];
        o[0] = acc[i][0] + bva.x + sa.x + na.x;
        o[1] = acc[i][1] + bva.y + sa.y + na.y;
        o[2] = acc[i][2] + bva.z + sa.z + na.z;
        o[3] = acc[i][3] + bva.w + sa.w + na.w;
        o[4] = acc[i][4] + bvb.x + sb.x + nb.x;
        o[5] = acc[i][5] + bvb.y + sb.y + nb.y;
        o[6] = acc[i][6] + bvb.z + sb.z + nb.z;
        o[7] = acc[i][7] + bvb.w + sb.w + nb.w;
        __half2 h0 = __floats2half2_rn(o[0], o[1]);
        __half2 h1 = __floats2half2_rn(o[2], o[3]);
        __half2 h2 = __floats2half2_rn(o[4], o[5]);
        __half2 h3 = __floats2half2_rn(o[6], o[7]);
        uint4 u;
        u.x = *(unsigned int*)&h0; u.y = *(unsigned int*)&h1;
        u.z = *(unsigned int*)&h2; u.w = *(unsigned int*)&h3;
        *(uint4*)&g_gatedh[(size_t)q * G2 + c0] = u;
#pragma unroll
        for (int k = 0; k < 8; k++) { cs[k] += o[k]; cq[k] += o[k] * o[k]; }
    }
    // lanes l and l^16 cover same columns (different row-groups) -> shfl combine
#pragma unroll
    for (int k = 0; k < 8; k++) {
        cs[k] += __shfl_xor_sync(0xffffffffu, cs[k], 16);
        cq[k] += __shfl_xor_sync(0xffffffffu, cq[k], 16);
    }
    int w = t >> 5;
    if ((t & 31) < 16) {
#pragma unroll
        for (int k = 0; k < 8; k++) {
            red[w * 256 + c0 + k]       = cs[k];
            red[w * 256 + G2 + c0 + k]  = cq[k];
        }
    }
    __syncthreads();
    {
        float s = 0.f;
#pragma unroll
        for (int w2 = 0; w2 < 8; w2++) s += red[w2 * 256 + t];
        atomicAdd(&g_stats1[t], s);
    }
}

// ---------------- BN1 + sigmoid*softplus + neighbor-sum + BN2 stats ----------------
// 16 atoms/block; each thread owns 4 columns (8B uint2 loads).
__global__ void __launch_bounds__(256) k_apply(const float* __restrict__ g1,
                                               const float* __restrict__ b1) {
    __shared__ float rs[16][AF];
    __shared__ float rq[16][AF];
    int t = threadIdx.x;
    int lg = t & 15;          // column group (4 cols)
    int al = t >> 4;          // atom within block (0..15)
    int n = blockIdx.x * 16 + al;
    int c0 = 4 * lg;
    const float inv = 1.f / (float)((size_t)NA * MM);

    float scF[4], shF[4], scC[4], shC[4];
#pragma unroll
    for (int k = 0; k < 4; k++) {
        int c = c0 + k;
        float mF = g_stats1[c] * inv;
        float vF = fmaxf(g_stats1[G2 + c] * inv - mF * mF, 0.f);
        float mC = g_stats1[AF + c] * inv;
        float vC = fmaxf(g_stats1[G2 + AF + c] * inv - mC * mC, 0.f);
        scF[k] = rsqrtf(vF + EPSB) * g1[c];
        shF[k] = b1[c] - mF * scF[k];
        scC[k] = rsqrtf(vC + EPSB) * g1[AF + c];
        shC[k] = b1[AF + c] - mC * scC[k];
    }

    size_t base = (size_t)n * MM * G2;
    float s[4] = {0.f, 0.f, 0.f, 0.f};
#pragma unroll
    for (int m = 0; m < MM; m++) {
        uint2 fu = *(const uint2*)&g_gatedh[base + m * G2 + c0];
        uint2 cu = *(const uint2*)&g_gatedh[base + m * G2 + AF + c0];
        float2 f01 = __half22float2(*(__half2*)&fu.x);
        float2 f23 = __half22float2(*(__half2*)&fu.y);
        float2 co01 = __half22float2(*(__half2*)&cu.x);
        float2 co23 = __half22float2(*(__half2*)&cu.y);
        s[0] += sigm(f01.x * scF[0] + shF[0]) * splus(co01.x * scC[0] + shC[0]);
        s[1] += sigm(f01.y * scF[1] + shF[1]) * splus(co01.y * scC[1] + shC[1]);
        s[2] += sigm(f23.x * scF[2] + shF[2]) * splus(co23.x * scC[2] + shC[2]);
        s[3] += sigm(f23.y * scF[3] + shF[3]) * splus(co23.y * scC[3] + shC[3]);
    }
    float4 sv; sv.x = s[0]; sv.y = s[1]; sv.z = s[2]; sv.w = s[3];
    *(float4*)&g_nbrsum[(size_t)n * AF + c0] = sv;
#pragma unroll
    for (int k = 0; k < 4; k++) {
        rs[al][c0 + k] = s[k];
        rq[al][c0 + k] = s[k] * s[k];
    }
    __syncthreads();
    if (t < AF) {
        float a = 0.f, b = 0.f;
#pragma unroll
        for (int k = 0; k < 16; k++) { a += rs[k][t]; b += rq[k][t]; }
        atomicAdd(&g_stats2[t], a);
        atomicAdd(&g_stats2[AF + t], b);
    }
}

// ---------------- BN2 + softplus(afea + y) + residual (float4) ----------------
__global__ void k_residual(const float* __restrict__ g2, const float* __restrict__ b2) {
    int idx = blockIdx.x * 256 + threadIdx.x;     // float4 index
    int c0 = (idx & 15) * 4;
    const float inv = 1.f / (float)NA;
    float sc[4], sh[4];
#pragma unroll
    for (int k = 0; k < 4; k++) {
        int c = c0 + k;
        float m = g_stats2[c] * inv;
        float v = fmaxf(g_stats2[AF + c] * inv - m * m, 0.f);
        sc[k] = rsqrtf(v + EPSB) * g2[c];
        sh[k] = b2[c] - m * sc[k];
    }
    float4 x = *(const float4*)&g_afea[(size_t)idx * 4];
    float4 y = *(const float4*)&g_nbrsum[(size_t)idx * 4];
    float4 o;
    o.x = splus(x.x + y.x * sc[0] + sh[0]) + x.x;
    o.y = splus(x.y + y.y * sc[1] + sh[1]) + x.y;
    o.z = splus(x.z + y.z * sc[2] + sh[2]) + x.z;
    o.w = splus(x.w + y.w * sc[3] + sh[3]) + x.w;
    *(float4*)&g_afea[(size_t)idx * 4] = o;
}

// ---------------- per-crystal mean pool + softplus ----------------
__global__ void k_pool() {
    int c = threadIdx.x;     // 64
    int b = blockIdx.x;      // 1024
    size_t base = (size_t)b * APC * AF;
    float s = 0.f;
    for (int a = 0; a < APC; a++) s += g_afea[base + a * AF + c];
    g_pool[b * AF + c] = splus(s * (1.f / (float)APC));
}

// ---------------- head ----------------
__global__ void k_head(const float* __restrict__ fc1w, const float* __restrict__ fc1b,
                       const float* __restrict__ o1w, const float* __restrict__ o1b,
                       const float* __restrict__ o2w, const float* __restrict__ o2b,
                       float* __restrict__ out_final, float* __restrict__ out_crys) {
    __shared__ float ps[AF];
    __shared__ float cs[HF];
    __shared__ float hs[AF];
    int t = threadIdx.x;     // 128
    int b = blockIdx.x;      // 1024
    if (t < AF) ps[t] = g_pool[b * AF + t];
    __syncthreads();
    {
        float a = fc1b[t];
        for (int k = 0; k < AF; k++) a += ps[k] * fc1w[k * HF + t];
        float cv = splus(a);
        cs[t] = cv;
        if (out_crys) out_crys[(size_t)b * HF + t] = cv;
    }
    __syncthreads();
    if (t < AF) {
        float a = o1b[t];
        for (int k = 0; k < HF; k++) a += cs[k] * o1w[k * AF + t];
        hs[t] = splus(a);
    }
    __syncthreads();
    if (t == 0) {
        float a = o2b[0];
        for (int k = 0; k < AF; k++) a += hs[k] * o2w[k];
        out_final[b] = a;
    }
}

// ---------------- launch ----------------
extern "C" void kernel_launch(void* const* d_in, const int* in_sizes, int n_in,
                              void* d_out, int out_size) {
    const float* atom_fea = (const float*)d_in[0];
    const float* nbr_fea  = (const float*)d_in[1];
    const int*   nbr_idx  = (const int*)d_in[2];
    const float* emb_w = (const float*)d_in[4];
    const float* emb_b = (const float*)d_in[5];
    const float* cw    = (const float*)d_in[6];
    const float* cb    = (const float*)d_in[7];
    const float* bn1g  = (const float*)d_in[8];
    const float* bn1b  = (const float*)d_in[9];
    const float* bn2g  = (const float*)d_in[10];
    const float* bn2b  = (const float*)d_in[11];
    const float* fc1w  = (const float*)d_in[12];
    const float* fc1b  = (const float*)d_in[13];
    const float* o1w   = (const float*)d_in[14];
    const float* o1b   = (const float*)d_in[15];
    const float* o2w   = (const float*)d_in[16];
    const float* o2b   = (const float*)d_in[17];

    float* out = (float*)d_out;
    float* crys = (out_size >= NC0 + NC0 * HF) ? out + NC0 : nullptr;

    const int selfnbr_smem = 64 * 256 * 4 + 64 * AF * 4;                     // 81920 B
    const int edge_smem = (NBR * G2 + 128 * NBR + 8 * 256) * 4;              // 50176 B
    cudaFuncSetAttribute(k_selfnbr, cudaFuncAttributeMaxDynamicSharedMemorySize, selfnbr_smem);
    cudaFuncSetAttribute(k_edgegated, cudaFuncAttributeMaxDynamicSharedMemorySize, edge_smem);

    k_embed<<<NA / 64, 256>>>(atom_fea, emb_w, emb_b);
    for (int i = 0; i < NCONV; i++) {
        const float* Wl = cw + (size_t)i * KTOT * G2;
        k_selfnbr<<<NA / 64, 256, selfnbr_smem>>>(Wl);
        k_edgegated<<<(NA * MM) / 128, 256, edge_smem>>>(Wl, cb + i * G2, nbr_fea, nbr_idx);
        k_apply<<<NA / 16, 256>>>(bn1g + i * G2, bn1b + i * G2);
        k_residual<<<(NA * AF / 4) / 256, 256>>>(bn2g + i * AF, bn2b + i * AF);
    }
    k_pool<<<NC0, 64>>>();
    k_head<<<NC0, 128>>>(fc1w, fc1b, o1w, o1b, o2w, o2b, out, crys);
}

// round 8
// speedup vs baseline: 1.5737x; 1.5737x over previous
#include <cuda_runtime.h>
#include <cuda_fp16.h>
#include <math.h>

#define NA   65536
#define MM   12
#define ORIG 92
#define NBR  41
#define AF   64
#define G2   128      // 2*AF
#define KTOT 169
#define NCONV 3
#define HF   128
#define NC0  1024     // crystals
#define APC  64       // atoms per crystal
#define EPSB 1e-5f

#define KP   48       // padded K for tf32 mma (41 -> 48)
#define ES   52       // Esm row stride (conflict-free for A-frag loads)
#define WS   136      // Wsm row stride (conflict-free for B-frag loads)
#define CS   132      // Csm row stride

// ---------------- scratch (device globals) ----------------
__device__ float  g_afea[(size_t)NA * AF];
__device__ float  g_sp[(size_t)NA * G2];
__device__ float  g_np[(size_t)NA * G2];
__device__ __half g_gatedh[(size_t)NA * MM * G2];    // 201 MB
__device__ float  g_nbrsum[(size_t)NA * AF];
__device__ float  g_stats1[2 * G2];
__device__ float  g_stats2[2 * AF];
__device__ float  g_pool[NC0 * AF];

__device__ __forceinline__ float splus(float x) {
    return fmaxf(x, 0.f) + __logf(1.f + __expf(-fabsf(x)));
}
__device__ __forceinline__ float sigm(float x) {
    return __fdividef(1.f, 1.f + __expf(-x));
}
__device__ __forceinline__ unsigned int f2tf(float x) {
    unsigned int r;
    asm("cvt.rna.tf32.f32 %0, %1;" : "=r"(r) : "f"(x));
    return r;
}

// ---------------- embedding: (NA x 92) @ (92 x 64) + b ----------------
__global__ void k_embed(const float* __restrict__ A, const float* __restrict__ W,
                        const float* __restrict__ bias) {
    __shared__ float Wsm[ORIG * AF];
    __shared__ float Asm[64 * ORIG];
    int t = threadIdx.x;
    int n0 = blockIdx.x * 64;
    for (int idx = t; idx < ORIG * AF; idx += 256) Wsm[idx] = W[idx];
    for (int idx = t; idx < 64 * ORIG; idx += 256) Asm[idx] = A[(size_t)n0 * ORIG + idx];
    __syncthreads();
    int c0 = (t & 15) * 4;
    int r0 = (t >> 4) * 4;
    float acc[4][4];
#pragma unroll
    for (int i = 0; i < 4; i++)
#pragma unroll
        for (int j = 0; j < 4; j++) acc[i][j] = 0.f;
    for (int f = 0; f < ORIG; f++) {
        float4 w = *(const float4*)&Wsm[f * AF + c0];
#pragma unroll
        for (int i = 0; i < 4; i++) {
            float a = Asm[(r0 + i) * ORIG + f];
            acc[i][0] += a * w.x; acc[i][1] += a * w.y;
            acc[i][2] += a * w.z; acc[i][3] += a * w.w;
        }
    }
    float4 bv = *(const float4*)&bias[c0];
#pragma unroll
    for (int i = 0; i < 4; i++) {
        float4 o;
        o.x = acc[i][0] + bv.x; o.y = acc[i][1] + bv.y;
        o.z = acc[i][2] + bv.z; o.w = acc[i][3] + bv.w;
        *(float4*)&g_afea[(size_t)(n0 + r0 + i) * AF + c0] = o;
    }
}

// ---------------- self + neighbor parts (also zeroes BN stats) ----------------
__global__ void k_selfnbr(const float* __restrict__ W) {
    extern __shared__ float sm[];
    float* Wsm = sm;               // [64][256]
    float* Asm = sm + 64 * 256;    // [64][64]
    int t = threadIdx.x;
    int n0 = blockIdx.x * 64;
    if (blockIdx.x == 0) {
        if (t < 2 * G2) g_stats1[t] = 0.f;
        if (t < 2 * AF) g_stats2[t] = 0.f;
    }
    for (int idx = t; idx < 64 * 256; idx += 256) {
        int f = idx >> 8, c = idx & 255;
        Wsm[idx] = (c < G2) ? W[f * G2 + c] : W[(AF + f) * G2 + (c - G2)];
    }
    {
        const float4* src = (const float4*)(g_afea + (size_t)n0 * AF);
        float4* dst = (float4*)Asm;
        for (int idx = t; idx < 64 * AF / 4; idx += 256) dst[idx] = src[idx];
    }
    __syncthreads();
    int c0 = (t & 31) * 4;
    int r0 = (t >> 5) * 8;
    float accS[8][4], accN[8][4];
#pragma unroll
    for (int i = 0; i < 8; i++)
#pragma unroll
        for (int j = 0; j < 4; j++) { accS[i][j] = 0.f; accN[i][j] = 0.f; }
    for (int f = 0; f < AF; f++) {
        float4 ws = *(const float4*)&Wsm[f * 256 + c0];
        float4 wn = *(const float4*)&Wsm[f * 256 + G2 + c0];
#pragma unroll
        for (int i = 0; i < 8; i++) {
            float a = Asm[(r0 + i) * AF + f];
            accS[i][0] += a * ws.x; accS[i][1] += a * ws.y;
            accS[i][2] += a * ws.z; accS[i][3] += a * ws.w;
            accN[i][0] += a * wn.x; accN[i][1] += a * wn.y;
            accN[i][2] += a * wn.z; accN[i][3] += a * wn.w;
        }
    }
#pragma unroll
    for (int i = 0; i < 8; i++) {
        size_t n = (size_t)(n0 + r0 + i);
        float4 os; os.x = accS[i][0]; os.y = accS[i][1]; os.z = accS[i][2]; os.w = accS[i][3];
        float4 on; on.x = accN[i][0]; on.y = accN[i][1]; on.z = accN[i][2]; on.w = accN[i][3];
        *(float4*)&g_sp[n * G2 + c0] = os;
        *(float4*)&g_np[n * G2 + c0] = on;
    }
}

// ---------------- edge GEMM (tf32 mma) + assemble gated (fp16) + BN1 stats ----------------
// 64 edges x 128 cols per block, 8 warps. Warps 0-3: rows 16w, cols 0-63;
// warps 4-7: rows 16(w-4), cols 64-127. K = 41 padded to 48, 6 k-steps of m16n8k8.
__global__ void __launch_bounds__(256) k_edgegated(
        const float* __restrict__ W, const float* __restrict__ bias,
        const float* __restrict__ nbr_fea, const int* __restrict__ nbr_idx) {
    extern __shared__ float sm[];
    float* Wsm = sm;                       // [48][WS]   6528 floats
    float* Esm = sm + KP * WS;             // [64][ES]   3328 floats
    float* Csm = sm;                       // [64][CS]   8448 floats (reuses W/E region)
    float* red = sm + KP * WS + 64 * ES;   // [2][8][128] 2048 floats
    int t = threadIdx.x;
    int q0 = blockIdx.x * 64;

    // load W edge part (rows 41..47 zero) and E tile (cols 41..47 zero)
    for (int idx = t; idx < KP * G2; idx += 256) {
        int f = idx >> 7, c = idx & 127;
        Wsm[f * WS + c] = (f < NBR) ? W[G2 * G2 + f * G2 + c] : 0.f;
    }
    for (int idx = t; idx < 64 * KP; idx += 256) {
        int e = idx / KP, f = idx - e * KP;
        Esm[e * ES + f] = (f < NBR) ? nbr_fea[(size_t)(q0 + e) * NBR + f] : 0.f;
    }
    __syncthreads();

    int lane = t & 31;
    int w = t >> 5;
    int m0 = (w & 3) * 16;
    int nc0 = (w >> 2) * 64;
    int g = lane >> 2;       // 0..7
    int tg = lane & 3;       // 0..3

    float d[8][4];
#pragma unroll
    for (int nt = 0; nt < 8; nt++)
#pragma unroll
        for (int k = 0; k < 4; k++) d[nt][k] = 0.f;

#pragma unroll
    for (int kt = 0; kt < 6; kt++) {
        int kk = kt * 8;
        unsigned int a0 = f2tf(Esm[(m0 + g) * ES + kk + tg]);
        unsigned int a1 = f2tf(Esm[(m0 + g + 8) * ES + kk + tg]);
        unsigned int a2 = f2tf(Esm[(m0 + g) * ES + kk + tg + 4]);
        unsigned int a3 = f2tf(Esm[(m0 + g + 8) * ES + kk + tg + 4]);
#pragma unroll
        for (int nt = 0; nt < 8; nt++) {
            int nc = nc0 + nt * 8;
            unsigned int b0 = f2tf(Wsm[(kk + tg) * WS + nc + g]);
            unsigned int b1 = f2tf(Wsm[(kk + tg + 4) * WS + nc + g]);
            asm volatile(
                "mma.sync.aligned.m16n8k8.row.col.f32.tf32.tf32.f32 "
                "{%0,%1,%2,%3}, {%4,%5,%6,%7}, {%8,%9}, {%0,%1,%2,%3};\n"
                : "+f"(d[nt][0]), "+f"(d[nt][1]), "+f"(d[nt][2]), "+f"(d[nt][3])
                : "r"(a0), "r"(a1), "r"(a2), "r"(a3), "r"(b0), "r"(b1));
        }
    }
    __syncthreads();   // W/E dead; reuse region as Csm

    // spill C fragments to smem: c0,c1 -> (row, 2*tg), c2,c3 -> (row+8, 2*tg)
#pragma unroll
    for (int nt = 0; nt < 8; nt++) {
        int c = nc0 + nt * 8 + 2 * tg;
        float2 lo; lo.x = d[nt][0]; lo.y = d[nt][1];
        float2 hi; hi.x = d[nt][2]; hi.y = d[nt][3];
        *(float2*)&Csm[(m0 + g) * CS + c] = lo;
        *(float2*)&Csm[(m0 + g + 8) * CS + c] = hi;
    }
    __syncthreads();

    // epilogue: add bias + sp + np, fp16 store, BN1 stats (R2 layout)
    int c0 = (t & 31) * 4;
    int r0 = (t >> 5) * 8;
    float4 bv = *(const float4*)&bias[c0];
    float cs0 = 0, cs1 = 0, cs2 = 0, cs3 = 0;
    float cq0 = 0, cq1 = 0, cq2 = 0, cq3 = 0;
#pragma unroll
    for (int i = 0; i < 8; i++) {
        int row = r0 + i;
        int q = q0 + row;
        int n = q / MM;
        int j = __ldg(&nbr_idx[q]);
        float4 a = *(const float4*)&Csm[row * CS + c0];
        float4 spv = *(const float4*)&g_sp[(size_t)n * G2 + c0];
        float4 npv = *(const float4*)&g_np[(size_t)j * G2 + c0];
        float4 o;
        o.x = a.x + bv.x + spv.x + npv.x;
        o.y = a.y + bv.y + spv.y + npv.y;
        o.z = a.z + bv.z + spv.z + npv.z;
        o.w = a.w + bv.w + spv.w + npv.w;
        __half2 h01 = __floats2half2_rn(o.x, o.y);
        __half2 h23 = __floats2half2_rn(o.z, o.w);
        uint2 u;
        u.x = *(unsigned int*)&h01;
        u.y = *(unsigned int*)&h23;
        *(uint2*)&g_gatedh[(size_t)q * G2 + c0] = u;
        cs0 += o.x; cq0 += o.x * o.x;
        cs1 += o.y; cq1 += o.y * o.y;
        cs2 += o.z; cq2 += o.z * o.z;
        cs3 += o.w; cq3 += o.w * o.w;
    }
    int rg = t >> 5;
    red[0 * 1024 + rg * G2 + c0 + 0] = cs0; red[1 * 1024 + rg * G2 + c0 + 0] = cq0;
    red[0 * 1024 + rg * G2 + c0 + 1] = cs1; red[1 * 1024 + rg * G2 + c0 + 1] = cq1;
    red[0 * 1024 + rg * G2 + c0 + 2] = cs2; red[1 * 1024 + rg * G2 + c0 + 2] = cq2;
    red[0 * 1024 + rg * G2 + c0 + 3] = cs3; red[1 * 1024 + rg * G2 + c0 + 3] = cq3;
    __syncthreads();
    if (t < G2) {
        float s = 0.f, ss = 0.f;
#pragma unroll
        for (int r = 0; r < 8; r++) { s += red[r * G2 + t]; ss += red[1024 + r * G2 + t]; }
        atomicAdd(&g_stats1[t], s);
        atomicAdd(&g_stats1[G2 + t], ss);
    }
}

// ---------------- BN1 + sigmoid*softplus + neighbor-sum + BN2 stats ----------------
// (R2-measured version: 8 atoms/block, 2 cols/thread, regs 32, occ 91%)
__global__ void k_apply(const float* __restrict__ g1, const float* __restrict__ b1) {
    __shared__ float rs[8][AF];
    __shared__ float rq[8][AF];
    int t = threadIdx.x;
    int cp = t & 31;
    int al = t >> 5;
    int n = blockIdx.x * 8 + al;
    int c0 = 2 * cp, c1 = c0 + 1;
    const float inv = 1.f / (float)((size_t)NA * MM);

    float mF0 = g_stats1[c0] * inv;
    float vF0 = fmaxf(g_stats1[G2 + c0] * inv - mF0 * mF0, 0.f);
    float mF1 = g_stats1[c1] * inv;
    float vF1 = fmaxf(g_stats1[G2 + c1] * inv - mF1 * mF1, 0.f);
    float mC0 = g_stats1[AF + c0] * inv;
    float vC0 = fmaxf(g_stats1[G2 + AF + c0] * inv - mC0 * mC0, 0.f);
    float mC1 = g_stats1[AF + c1] * inv;
    float vC1 = fmaxf(g_stats1[G2 + AF + c1] * inv - mC1 * mC1, 0.f);
    float scF0 = rsqrtf(vF0 + EPSB) * g1[c0];
    float shF0 = b1[c0] - mF0 * scF0;
    float scF1 = rsqrtf(vF1 + EPSB) * g1[c1];
    float shF1 = b1[c1] - mF1 * scF1;
    float scC0 = rsqrtf(vC0 + EPSB) * g1[AF + c0];
    float shC0 = b1[AF + c0] - mC0 * scC0;
    float scC1 = rsqrtf(vC1 + EPSB) * g1[AF + c1];
    float shC1 = b1[AF + c1] - mC1 * scC1;

    size_t base = (size_t)n * MM * G2;
    float s0 = 0.f, s1 = 0.f;
#pragma unroll
    for (int m = 0; m < MM; m++) {
        __half2 flh = *(const __half2*)&g_gatedh[base + m * G2 + c0];
        __half2 coh = *(const __half2*)&g_gatedh[base + m * G2 + AF + c0];
        float2 fl = __half22float2(flh);
        float2 co = __half22float2(coh);
        s0 += sigm(fl.x * scF0 + shF0) * splus(co.x * scC0 + shC0);
        s1 += sigm(fl.y * scF1 + shF1) * splus(co.y * scC1 + shC1);
    }
    g_nbrsum[(size_t)n * AF + c0] = s0;
    g_nbrsum[(size_t)n * AF + c1] = s1;
    rs[al][c0] = s0; rs[al][c1] = s1;
    rq[al][c0] = s0 * s0; rq[al][c1] = s1 * s1;
    __syncthreads();
    if (t < AF) {
        float a = 0.f, b = 0.f;
#pragma unroll
        for (int k = 0; k < 8; k++) { a += rs[k][t]; b += rq[k][t]; }
        atomicAdd(&g_stats2[t], a);
        atomicAdd(&g_stats2[AF + t], b);
    }
}

// ---------------- BN2 + softplus(afea + y) + residual ----------------
__global__ void k_residual(const float* __restrict__ g2, const float* __restrict__ b2) {
    int idx = blockIdx.x * 256 + threadIdx.x;
    int c = idx & 63;
    const float inv = 1.f / (float)NA;
    float m = g_stats2[c] * inv;
    float v = fmaxf(g_stats2[AF + c] * inv - m * m, 0.f);
    float sc = rsqrtf(v + EPSB) * g2[c];
    float sh = b2[c] - m * sc;
    float x = g_afea[idx];
    float y = g_nbrsum[idx] * sc + sh;
    g_afea[idx] = splus(x + y) + x;
}

// ---------------- per-crystal mean pool + softplus ----------------
__global__ void k_pool() {
    int c = threadIdx.x;     // 64
    int b = blockIdx.x;      // 1024
    size_t base = (size_t)b * APC * AF;
    float s = 0.f;
    for (int a = 0; a < APC; a++) s += g_afea[base + a * AF + c];
    g_pool[b * AF + c] = splus(s * (1.f / (float)APC));
}

// ---------------- head ----------------
__global__ void k_head(const float* __restrict__ fc1w, const float* __restrict__ fc1b,
                       const float* __restrict__ o1w, const float* __restrict__ o1b,
                       const float* __restrict__ o2w, const float* __restrict__ o2b,
                       float* __restrict__ out_final, float* __restrict__ out_crys) {
    __shared__ float ps[AF];
    __shared__ float cs[HF];
    __shared__ float hs[AF];
    int t = threadIdx.x;     // 128
    int b = blockIdx.x;      // 1024
    if (t < AF) ps[t] = g_pool[b * AF + t];
    __syncthreads();
    {
        float a = fc1b[t];
        for (int k = 0; k < AF; k++) a += ps[k] * fc1w[k * HF + t];
        float cv = splus(a);
        cs[t] = cv;
        if (out_crys) out_crys[(size_t)b * HF + t] = cv;
    }
    __syncthreads();
    if (t < AF) {
        float a = o1b[t];
        for (int k = 0; k < HF; k++) a += cs[k] * o1w[k * AF + t];
        hs[t] = splus(a);
    }
    __syncthreads();
    if (t == 0) {
        float a = o2b[0];
        for (int k = 0; k < AF; k++) a += hs[k] * o2w[k];
        out_final[b] = a;
    }
}

// ---------------- launch ----------------
extern "C" void kernel_launch(void* const* d_in, const int* in_sizes, int n_in,
                              void* d_out, int out_size) {
    const float* atom_fea = (const float*)d_in[0];
    const float* nbr_fea  = (const float*)d_in[1];
    const int*   nbr_idx  = (const int*)d_in[2];
    const float* emb_w = (const float*)d_in[4];
    const float* emb_b = (const float*)d_in[5];
    const float* cw    = (const float*)d_in[6];
    const float* cb    = (const float*)d_in[7];
    const float* bn1g  = (const float*)d_in[8];
    const float* bn1b  = (const float*)d_in[9];
    const float* bn2g  = (const float*)d_in[10];
    const float* bn2b  = (const float*)d_in[11];
    const float* fc1w  = (const float*)d_in[12];
    const float* fc1b  = (const float*)d_in[13];
    const float* o1w   = (const float*)d_in[14];
    const float* o1b   = (const float*)d_in[15];
    const float* o2w   = (const float*)d_in[16];
    const float* o2b   = (const float*)d_in[17];

    float* out = (float*)d_out;
    float* crys = (out_size >= NC0 + NC0 * HF) ? out + NC0 : nullptr;

    const int selfnbr_smem = 64 * 256 * 4 + 64 * AF * 4;                 // 81920 B
    const int edge_smem = (KP * WS + 64 * ES + 2 * 8 * G2) * 4;          // 47616 B
    cudaFuncSetAttribute(k_selfnbr, cudaFuncAttributeMaxDynamicSharedMemorySize, selfnbr_smem);
    cudaFuncSetAttribute(k_edgegated, cudaFuncAttributeMaxDynamicSharedMemorySize, edge_smem);

    k_embed<<<NA / 64, 256>>>(atom_fea, emb_w, emb_b);
    for (int i = 0; i < NCONV; i++) {
        const float* Wl = cw + (size_t)i * KTOT * G2;
        k_selfnbr<<<NA / 64, 256, selfnbr_smem>>>(Wl);
        k_edgegated<<<(NA * MM) / 64, 256, edge_smem>>>(Wl, cb + i * G2, nbr_fea, nbr_idx);
        k_apply<<<NA / 8, 256>>>(bn1g + i * G2, bn1b + i * G2);
        k_residual<<<(NA * AF) / 256, 256>>>(bn2g + i * AF, bn2b + i * AF);
    }
    k_pool<<<NC0, 64>>>();
    k_head<<<NC0, 128>>>(fc1w, fc1b, o1w, o1b, o2w, o2b, out, crys);
}

// round 9
// speedup vs baseline: 1.6377x; 1.0406x over previous
#include <cuda_runtime.h>
#include <cuda_fp16.h>
#include <math.h>

#define NA   65536
#define MM   12
#define ORIG 92
#define NBR  41
#define AF   64
#define G2   128      // 2*AF
#define KTOT 169
#define NCONV 3
#define HF   128
#define NC0  1024     // crystals
#define APC  64       // atoms per crystal
#define EPSB 1e-5f

#define KP   48       // padded K for tf32 mma (41 -> 48)
#define ES   52       // Esm row stride
#define WS   136      // Wsm row stride (edge kernel)
#define CS   132      // Csm row stride
#define AS   68       // Asm row stride (selfnbr kernel)
#define WS2  136      // Wsm row stride (selfnbr kernel)

// ---------------- scratch (device globals) ----------------
__device__ float  g_afea[(size_t)NA * AF];
__device__ __half g_sph[(size_t)NA * G2];            // 16.8 MB fp16 self part
__device__ __half g_nph[(size_t)NA * G2];            // 16.8 MB fp16 neighbor part
__device__ __half g_gatedh[(size_t)NA * MM * G2];    // 201 MB
__device__ float  g_nbrsum[(size_t)NA * AF];
__device__ float  g_stats1[2 * G2];
__device__ float  g_stats2[2 * AF];
__device__ float  g_pool[NC0 * AF];

__device__ __forceinline__ float splus(float x) {
    return fmaxf(x, 0.f) + __logf(1.f + __expf(-fabsf(x)));
}
__device__ __forceinline__ float sigm(float x) {
    return __fdividef(1.f, 1.f + __expf(-x));
}
__device__ __forceinline__ unsigned int f2tf(float x) {
    unsigned int r;
    asm("cvt.rna.tf32.f32 %0, %1;" : "=r"(r) : "f"(x));
    return r;
}

// ---------------- embedding: (NA x 92) @ (92 x 64) + b ----------------
__global__ void k_embed(const float* __restrict__ A, const float* __restrict__ W,
                        const float* __restrict__ bias) {
    __shared__ float Wsm[ORIG * AF];
    __shared__ float Asm[64 * ORIG];
    int t = threadIdx.x;
    int n0 = blockIdx.x * 64;
    for (int idx = t; idx < ORIG * AF; idx += 256) Wsm[idx] = W[idx];
    for (int idx = t; idx < 64 * ORIG; idx += 256) Asm[idx] = A[(size_t)n0 * ORIG + idx];
    __syncthreads();
    int c0 = (t & 15) * 4;
    int r0 = (t >> 4) * 4;
    float acc[4][4];
#pragma unroll
    for (int i = 0; i < 4; i++)
#pragma unroll
        for (int j = 0; j < 4; j++) acc[i][j] = 0.f;
    for (int f = 0; f < ORIG; f++) {
        float4 w = *(const float4*)&Wsm[f * AF + c0];
#pragma unroll
        for (int i = 0; i < 4; i++) {
            float a = Asm[(r0 + i) * ORIG + f];
            acc[i][0] += a * w.x; acc[i][1] += a * w.y;
            acc[i][2] += a * w.z; acc[i][3] += a * w.w;
        }
    }
    float4 bv = *(const float4*)&bias[c0];
#pragma unroll
    for (int i = 0; i < 4; i++) {
        float4 o;
        o.x = acc[i][0] + bv.x; o.y = acc[i][1] + bv.y;
        o.z = acc[i][2] + bv.z; o.w = acc[i][3] + bv.w;
        *(float4*)&g_afea[(size_t)(n0 + r0 + i) * AF + c0] = o;
    }
}

// ---------------- self+nbr parts via tf32 MMA; fp16 outputs ----------------
// grid (NA/64, 2): y=0 -> self (W rows 0..63 -> g_sph), y=1 -> nbr (W rows 64..127 -> g_nph)
// 8 warps: m0=(w&3)*16, nc0=(w>>2)*64; per warp 16x64, K=64 (8 ksteps of m16n8k8).
__global__ void __launch_bounds__(256) k_selfnbr(const float* __restrict__ W) {
    extern __shared__ float sm[];
    float* Wsm = sm;                 // [64][WS2] 8704 floats
    float* Asm = sm + 64 * WS2;      // [64][AS]  4352 floats
    int t = threadIdx.x;
    int n0 = blockIdx.x * 64;
    int half = blockIdx.y;
    if (blockIdx.x == 0 && half == 0) {
        if (t < 2 * G2) g_stats1[t] = 0.f;
        if (t < 2 * AF) g_stats2[t] = 0.f;
    }
    for (int idx = t; idx < 64 * G2; idx += 256) {
        int f = idx >> 7, c = idx & 127;
        Wsm[f * WS2 + c] = W[(half * AF + f) * G2 + c];
    }
    for (int idx = t; idx < 64 * AF; idx += 256) {
        int r = idx >> 6, c = idx & 63;
        Asm[r * AS + c] = g_afea[(size_t)(n0 + r) * AF + c];
    }
    __syncthreads();

    int lane = t & 31;
    int w = t >> 5;
    int m0 = (w & 3) * 16;
    int nc0 = (w >> 2) * 64;
    int g = lane >> 2;
    int tg = lane & 3;

    float d[8][4];
#pragma unroll
    for (int nt = 0; nt < 8; nt++)
#pragma unroll
        for (int k = 0; k < 4; k++) d[nt][k] = 0.f;

#pragma unroll
    for (int kt = 0; kt < 8; kt++) {
        int kk = kt * 8;
        unsigned int a0 = f2tf(Asm[(m0 + g) * AS + kk + tg]);
        unsigned int a1 = f2tf(Asm[(m0 + g + 8) * AS + kk + tg]);
        unsigned int a2 = f2tf(Asm[(m0 + g) * AS + kk + tg + 4]);
        unsigned int a3 = f2tf(Asm[(m0 + g + 8) * AS + kk + tg + 4]);
#pragma unroll
        for (int nt = 0; nt < 8; nt++) {
            int nc = nc0 + nt * 8;
            unsigned int b0 = f2tf(Wsm[(kk + tg) * WS2 + nc + g]);
            unsigned int b1 = f2tf(Wsm[(kk + tg + 4) * WS2 + nc + g]);
            asm volatile(
                "mma.sync.aligned.m16n8k8.row.col.f32.tf32.tf32.f32 "
                "{%0,%1,%2,%3}, {%4,%5,%6,%7}, {%8,%9}, {%0,%1,%2,%3};\n"
                : "+f"(d[nt][0]), "+f"(d[nt][1]), "+f"(d[nt][2]), "+f"(d[nt][3])
                : "r"(a0), "r"(a1), "r"(a2), "r"(a3), "r"(b0), "r"(b1));
        }
    }

    __half* out = half ? g_nph : g_sph;
#pragma unroll
    for (int nt = 0; nt < 8; nt++) {
        int c = nc0 + nt * 8 + 2 * tg;
        __half2 lo = __floats2half2_rn(d[nt][0], d[nt][1]);
        __half2 hi = __floats2half2_rn(d[nt][2], d[nt][3]);
        *(__half2*)&out[(size_t)(n0 + m0 + g) * G2 + c] = lo;
        *(__half2*)&out[(size_t)(n0 + m0 + g + 8) * G2 + c] = hi;
    }
}

// ---------------- edge GEMM (tf32 mma) + assemble gated (fp16) + BN1 stats ----------------
__global__ void __launch_bounds__(256) k_edgegated(
        const float* __restrict__ W, const float* __restrict__ bias,
        const float* __restrict__ nbr_fea, const int* __restrict__ nbr_idx) {
    extern __shared__ float sm[];
    float* Wsm = sm;                       // [48][WS]   6528 floats
    float* Esm = sm + KP * WS;             // [64][ES]   3328 floats
    float* Csm = sm;                       // [64][CS]   8448 floats (reuses W/E region)
    float* red = sm + KP * WS + 64 * ES;   // [2][8][128] 2048 floats
    int t = threadIdx.x;
    int q0 = blockIdx.x * 64;

    for (int idx = t; idx < KP * G2; idx += 256) {
        int f = idx >> 7, c = idx & 127;
        Wsm[f * WS + c] = (f < NBR) ? W[G2 * G2 + f * G2 + c] : 0.f;
    }
    for (int idx = t; idx < 64 * KP; idx += 256) {
        int e = idx / KP, f = idx - e * KP;
        Esm[e * ES + f] = (f < NBR) ? nbr_fea[(size_t)(q0 + e) * NBR + f] : 0.f;
    }
    __syncthreads();

    int lane = t & 31;
    int w = t >> 5;
    int m0 = (w & 3) * 16;
    int nc0 = (w >> 2) * 64;
    int g = lane >> 2;
    int tg = lane & 3;

    float d[8][4];
#pragma unroll
    for (int nt = 0; nt < 8; nt++)
#pragma unroll
        for (int k = 0; k < 4; k++) d[nt][k] = 0.f;

#pragma unroll
    for (int kt = 0; kt < 6; kt++) {
        int kk = kt * 8;
        unsigned int a0 = f2tf(Esm[(m0 + g) * ES + kk + tg]);
        unsigned int a1 = f2tf(Esm[(m0 + g + 8) * ES + kk + tg]);
        unsigned int a2 = f2tf(Esm[(m0 + g) * ES + kk + tg + 4]);
        unsigned int a3 = f2tf(Esm[(m0 + g + 8) * ES + kk + tg + 4]);
#pragma unroll
        for (int nt = 0; nt < 8; nt++) {
            int nc = nc0 + nt * 8;
            unsigned int b0 = f2tf(Wsm[(kk + tg) * WS + nc + g]);
            unsigned int b1 = f2tf(Wsm[(kk + tg + 4) * WS + nc + g]);
            asm volatile(
                "mma.sync.aligned.m16n8k8.row.col.f32.tf32.tf32.f32 "
                "{%0,%1,%2,%3}, {%4,%5,%6,%7}, {%8,%9}, {%0,%1,%2,%3};\n"
                : "+f"(d[nt][0]), "+f"(d[nt][1]), "+f"(d[nt][2]), "+f"(d[nt][3])
                : "r"(a0), "r"(a1), "r"(a2), "r"(a3), "r"(b0), "r"(b1));
        }
    }
    __syncthreads();   // W/E dead; reuse region as Csm

#pragma unroll
    for (int nt = 0; nt < 8; nt++) {
        int c = nc0 + nt * 8 + 2 * tg;
        float2 lo; lo.x = d[nt][0]; lo.y = d[nt][1];
        float2 hi; hi.x = d[nt][2]; hi.y = d[nt][3];
        *(float2*)&Csm[(m0 + g) * CS + c] = lo;
        *(float2*)&Csm[(m0 + g + 8) * CS + c] = hi;
    }
    __syncthreads();

    // epilogue: add bias + sp(fp16) + np(fp16), fp16 store, BN1 stats
    int c0 = (t & 31) * 4;
    int r0 = (t >> 5) * 8;
    float4 bv = *(const float4*)&bias[c0];
    float cs0 = 0, cs1 = 0, cs2 = 0, cs3 = 0;
    float cq0 = 0, cq1 = 0, cq2 = 0, cq3 = 0;
#pragma unroll
    for (int i = 0; i < 8; i++) {
        int row = r0 + i;
        int q = q0 + row;
        int n = q / MM;
        int j = __ldg(&nbr_idx[q]);
        float4 a = *(const float4*)&Csm[row * CS + c0];
        uint2 su = *(const uint2*)&g_sph[(size_t)n * G2 + c0];
        uint2 nu = *(const uint2*)&g_nph[(size_t)j * G2 + c0];
        float2 sA = __half22float2(*(__half2*)&su.x);
        float2 sB = __half22float2(*(__half2*)&su.y);
        float2 nA = __half22float2(*(__half2*)&nu.x);
        float2 nB = __half22float2(*(__half2*)&nu.y);
        float4 o;
        o.x = a.x + bv.x + sA.x + nA.x;
        o.y = a.y + bv.y + sA.y + nA.y;
        o.z = a.z + bv.z + sB.x + nB.x;
        o.w = a.w + bv.w + sB.y + nB.y;
        __half2 h01 = __floats2half2_rn(o.x, o.y);
        __half2 h23 = __floats2half2_rn(o.z, o.w);
        uint2 u;
        u.x = *(unsigned int*)&h01;
        u.y = *(unsigned int*)&h23;
        *(uint2*)&g_gatedh[(size_t)q * G2 + c0] = u;
        cs0 += o.x; cq0 += o.x * o.x;
        cs1 += o.y; cq1 += o.y * o.y;
        cs2 += o.z; cq2 += o.z * o.z;
        cs3 += o.w; cq3 += o.w * o.w;
    }
    int rg = t >> 5;
    red[0 * 1024 + rg * G2 + c0 + 0] = cs0; red[1 * 1024 + rg * G2 + c0 + 0] = cq0;
    red[0 * 1024 + rg * G2 + c0 + 1] = cs1; red[1 * 1024 + rg * G2 + c0 + 1] = cq1;
    red[0 * 1024 + rg * G2 + c0 + 2] = cs2; red[1 * 1024 + rg * G2 + c0 + 2] = cq2;
    red[0 * 1024 + rg * G2 + c0 + 3] = cs3; red[1 * 1024 + rg * G2 + c0 + 3] = cq3;
    __syncthreads();
    if (t < G2) {
        float s = 0.f, ss = 0.f;
#pragma unroll
        for (int r = 0; r < 8; r++) { s += red[r * G2 + t]; ss += red[1024 + r * G2 + t]; }
        atomicAdd(&g_stats1[t], s);
        atomicAdd(&g_stats1[G2 + t], ss);
    }
}

// ---------------- BN1 + sigmoid*softplus + neighbor-sum + BN2 stats ----------------
__global__ void k_apply(const float* __restrict__ g1, const float* __restrict__ b1) {
    __shared__ float rs[8][AF];
    __shared__ float rq[8][AF];
    int t = threadIdx.x;
    int cp = t & 31;
    int al = t >> 5;
    int n = blockIdx.x * 8 + al;
    int c0 = 2 * cp, c1 = c0 + 1;
    const float inv = 1.f / (float)((size_t)NA * MM);

    float mF0 = g_stats1[c0] * inv;
    float vF0 = fmaxf(g_stats1[G2 + c0] * inv - mF0 * mF0, 0.f);
    float mF1 = g_stats1[c1] * inv;
    float vF1 = fmaxf(g_stats1[G2 + c1] * inv - mF1 * mF1, 0.f);
    float mC0 = g_stats1[AF + c0] * inv;
    float vC0 = fmaxf(g_stats1[G2 + AF + c0] * inv - mC0 * mC0, 0.f);
    float mC1 = g_stats1[AF + c1] * inv;
    float vC1 = fmaxf(g_stats1[G2 + AF + c1] * inv - mC1 * mC1, 0.f);
    float scF0 = rsqrtf(vF0 + EPSB) * g1[c0];
    float shF0 = b1[c0] - mF0 * scF0;
    float scF1 = rsqrtf(vF1 + EPSB) * g1[c1];
    float shF1 = b1[c1] - mF1 * scF1;
    float scC0 = rsqrtf(vC0 + EPSB) * g1[AF + c0];
    float shC0 = b1[AF + c0] - mC0 * scC0;
    float scC1 = rsqrtf(vC1 + EPSB) * g1[AF + c1];
    float shC1 = b1[AF + c1] - mC1 * scC1;

    size_t base = (size_t)n * MM * G2;
    float s0 = 0.f, s1 = 0.f;
#pragma unroll
    for (int m = 0; m < MM; m++) {
        __half2 flh = *(const __half2*)&g_gatedh[base + m * G2 + c0];
        __half2 coh = *(const __half2*)&g_gatedh[base + m * G2 + AF + c0];
        float2 fl = __half22float2(flh);
        float2 co = __half22float2(coh);
        s0 += sigm(fl.x * scF0 + shF0) * splus(co.x * scC0 + shC0);
        s1 += sigm(fl.y * scF1 + shF1) * splus(co.y * scC1 + shC1);
    }
    g_nbrsum[(size_t)n * AF + c0] = s0;
    g_nbrsum[(size_t)n * AF + c1] = s1;
    rs[al][c0] = s0; rs[al][c1] = s1;
    rq[al][c0] = s0 * s0; rq[al][c1] = s1 * s1;
    __syncthreads();
    if (t < AF) {
        float a = 0.f, b = 0.f;
#pragma unroll
        for (int k = 0; k < 8; k++) { a += rs[k][t]; b += rq[k][t]; }
        atomicAdd(&g_stats2[t], a);
        atomicAdd(&g_stats2[AF + t], b);
    }
}

// ---------------- BN2 + softplus(afea + y) + residual ----------------
__global__ void k_residual(const float* __restrict__ g2, const float* __restrict__ b2) {
    int idx = blockIdx.x * 256 + threadIdx.x;
    int c = idx & 63;
    const float inv = 1.f / (float)NA;
    float m = g_stats2[c] * inv;
    float v = fmaxf(g_stats2[AF + c] * inv - m * m, 0.f);
    float sc = rsqrtf(v + EPSB) * g2[c];
    float sh = b2[c] - m * sc;
    float x = g_afea[idx];
    float y = g_nbrsum[idx] * sc + sh;
    g_afea[idx] = splus(x + y) + x;
}

// ---------------- per-crystal mean pool + softplus ----------------
__global__ void k_pool() {
    int c = threadIdx.x;     // 64
    int b = blockIdx.x;      // 1024
    size_t base = (size_t)b * APC * AF;
    float s = 0.f;
    for (int a = 0; a < APC; a++) s += g_afea[base + a * AF + c];
    g_pool[b * AF + c] = splus(s * (1.f / (float)APC));
}

// ---------------- head ----------------
__global__ void k_head(const float* __restrict__ fc1w, const float* __restrict__ fc1b,
                       const float* __restrict__ o1w, const float* __restrict__ o1b,
                       const float* __restrict__ o2w, const float* __restrict__ o2b,
                       float* __restrict__ out_final, float* __restrict__ out_crys) {
    __shared__ float ps[AF];
    __shared__ float cs[HF];
    __shared__ float hs[AF];
    int t = threadIdx.x;     // 128
    int b = blockIdx.x;      // 1024
    if (t < AF) ps[t] = g_pool[b * AF + t];
    __syncthreads();
    {
        float a = fc1b[t];
        for (int k = 0; k < AF; k++) a += ps[k] * fc1w[k * HF + t];
        float cv = splus(a);
        cs[t] = cv;
        if (out_crys) out_crys[(size_t)b * HF + t] = cv;
    }
    __syncthreads();
    if (t < AF) {
        float a = o1b[t];
        for (int k = 0; k < HF; k++) a += cs[k] * o1w[k * AF + t];
        hs[t] = splus(a);
    }
    __syncthreads();
    if (t == 0) {
        float a = o2b[0];
        for (int k = 0; k < AF; k++) a += hs[k] * o2w[k];
        out_final[b] = a;
    }
}

// ---------------- launch ----------------
extern "C" void kernel_launch(void* const* d_in, const int* in_sizes, int n_in,
                              void* d_out, int out_size) {
    const float* atom_fea = (const float*)d_in[0];
    const float* nbr_fea  = (const float*)d_in[1];
    const int*   nbr_idx  = (const int*)d_in[2];
    const float* emb_w = (const float*)d_in[4];
    const float* emb_b = (const float*)d_in[5];
    const float* cw    = (const float*)d_in[6];
    const float* cb    = (const float*)d_in[7];
    const float* bn1g  = (const float*)d_in[8];
    const float* bn1b  = (const float*)d_in[9];
    const float* bn2g  = (const float*)d_in[10];
    const float* bn2b  = (const float*)d_in[11];
    const float* fc1w  = (const float*)d_in[12];
    const float* fc1b  = (const float*)d_in[13];
    const float* o1w   = (const float*)d_in[14];
    const float* o1b   = (const float*)d_in[15];
    const float* o2w   = (const float*)d_in[16];
    const float* o2b   = (const float*)d_in[17];

    float* out = (float*)d_out;
    float* crys = (out_size >= NC0 + NC0 * HF) ? out + NC0 : nullptr;

    const int selfnbr_smem = (64 * WS2 + 64 * AS) * 4;                   // 52224 B
    const int edge_smem = (KP * WS + 64 * ES + 2 * 8 * G2) * 4;          // 47616 B
    cudaFuncSetAttribute(k_selfnbr, cudaFuncAttributeMaxDynamicSharedMemorySize, selfnbr_smem);
    cudaFuncSetAttribute(k_edgegated, cudaFuncAttributeMaxDynamicSharedMemorySize, edge_smem);

    k_embed<<<NA / 64, 256>>>(atom_fea, emb_w, emb_b);
    for (int i = 0; i < NCONV; i++) {
        const float* Wl = cw + (size_t)i * KTOT * G2;
        k_selfnbr<<<dim3(NA / 64, 2), 256, selfnbr_smem>>>(Wl);
        k_edgegated<<<(NA * MM) / 64, 256, edge_smem>>>(Wl, cb + i * G2, nbr_fea, nbr_idx);
        k_apply<<<NA / 8, 256>>>(bn1g + i * G2, bn1b + i * G2);
        k_residual<<<(NA * AF) / 256, 256>>>(bn2g + i * AF, bn2b + i * AF);
    }
    k_pool<<<NC0, 64>>>();
    k_head<<<NC0, 128>>>(fc1w, fc1b, o1w, o1b, o2w, o2b, out, crys);
}